// round 2
// baseline (speedup 1.0000x reference)
#include <cuda_runtime.h>

// ---------------------------------------------------------------------------
// ColBERT scoring, fp32, f32x2-packed FMA SIMT GEMM baseline.
//   Q  = l2norm(Q_emb @ W^T)                       [B,32,128]
//   Dr = D_emb @ W^T ; Dn = l2norm(Dr * (ids!=0))  [B,1024,128]
//   score[b,q,t] = 2*Qn.Dn - 1 - dsq[t]  (q_sq==1, dsq = punct?1:0)
//   masked (attn) max over t, sum over q -> out[B]
// ---------------------------------------------------------------------------

#define B_   128
#define QL_  32
#define DL_  1024
#define H_   768
#define DIM_ 128
#define TB_  64            // doc tokens per CTA
#define KC_  16            // K chunk
#define NT_  (DL_/TB_)     // 16 tiles per batch
#define NCHUNK_ (H_/KC_)   // 48
#define NEG_ (-100000.0f)

__device__ float g_Qn[B_*QL_*DIM_];        // normalized queries
__device__ float g_partial[B_*QL_*NT_];    // per-(b,q,tile) max score

typedef unsigned long long u64;

__device__ __forceinline__ u64 pack2(float x, float y) {
    u64 r; asm("mov.b64 %0, {%1, %2};" : "=l"(r) : "f"(x), "f"(y)); return r;
}
__device__ __forceinline__ float2 unpack2(u64 v) {
    float2 r; asm("mov.b64 {%0, %1}, %2;" : "=f"(r.x), "=f"(r.y) : "l"(v)); return r;
}
__device__ __forceinline__ void fma2(u64& d, u64 a, u64 b) {
    asm("fma.rn.f32x2 %0, %1, %2, %0;" : "+l"(d) : "l"(a), "l"(b));
}

// ---------------------------------------------------------------------------
// Kernel 1: Q projection + L2 normalize.  One CTA per batch. M=32,N=128,K=768.
// ---------------------------------------------------------------------------
__global__ __launch_bounds__(256)
void q_kernel(const float* __restrict__ Qe, const float* __restrict__ W) {
    __shared__ float QsT[KC_][QL_+4];     // transposed: [k][q]
    __shared__ float WsT[KC_][DIM_];      // transposed: [k][d]
    const int b = blockIdx.x;
    const int tid = threadIdx.x;
    const int tx = tid & 15;              // dim group: d = tx*8 + j
    const int ty = tid >> 4;              // query group: q = ty*2 + i

    float acc[2][8];
#pragma unroll
    for (int i = 0; i < 2; i++)
#pragma unroll
        for (int j = 0; j < 8; j++) acc[i][j] = 0.0f;

    for (int c = 0; c < NCHUNK_; c++) {
        const int kc = c * KC_;
        __syncthreads();
        if (tid < 128) {
            int t = tid >> 2, kq = (tid & 3) * 4;
            float4 v = *(const float4*)(Qe + (b*QL_ + t)*H_ + kc + kq);
            QsT[kq+0][t] = v.x; QsT[kq+1][t] = v.y;
            QsT[kq+2][t] = v.z; QsT[kq+3][t] = v.w;
        }
#pragma unroll
        for (int r = 0; r < 2; r++) {
            int idx = tid*2 + r;
            int d = idx >> 2, kq = (idx & 3) * 4;
            float4 w = *(const float4*)(W + d*H_ + kc + kq);
            WsT[kq+0][d] = w.x; WsT[kq+1][d] = w.y;
            WsT[kq+2][d] = w.z; WsT[kq+3][d] = w.w;
        }
        __syncthreads();
#pragma unroll
        for (int kk = 0; kk < KC_; kk++) {
            float a0 = QsT[kk][ty*2+0];
            float a1 = QsT[kk][ty*2+1];
#pragma unroll
            for (int j = 0; j < 8; j++) {
                float bb = WsT[kk][tx*8+j];
                acc[0][j] += a0 * bb;
                acc[1][j] += a1 * bb;
            }
        }
    }

#pragma unroll
    for (int i = 0; i < 2; i++) {
        float ss = 0.0f;
#pragma unroll
        for (int j = 0; j < 8; j++) ss += acc[i][j]*acc[i][j];
#pragma unroll
        for (int m = 1; m < 16; m <<= 1) ss += __shfl_xor_sync(0xffffffffu, ss, m);
        float inv = rsqrtf(fmaxf(ss, 1e-24f));
        int q = ty*2 + i;
#pragma unroll
        for (int j = 0; j < 8; j++)
            g_Qn[(b*QL_ + q)*DIM_ + tx*8 + j] = acc[i][j] * inv;
    }
}

// ---------------------------------------------------------------------------
// Kernel 2: D projection (64x128 tile, K=768, double-buffered, f32x2 FMAs)
//           fused with normalize + scoring GEMM + masked per-query max.
// ---------------------------------------------------------------------------
struct __align__(16) SmemMain {
    float DsT[2][KC_][TB_+4];   // [k][t], padded
    float WsT[2][KC_][DIM_];    // [k][d]
};
struct __align__(16) SmemEpi {
    float DnT[DIM_][TB_+4];     // normalized D, transposed [d][t]
    float Qs[QL_][DIM_+1];      // Qn rows, padded
    float dsq[TB_];             // punct ? 1 : 0
    int   keep[TB_];            // attn mask
};

extern __shared__ char smem_raw[];

__global__ __launch_bounds__(256, 2)
void d_kernel(const float* __restrict__ De, const int* __restrict__ ids,
              const int* __restrict__ attn, const float* __restrict__ W) {
    SmemMain* sm = (SmemMain*)smem_raw;
    SmemEpi*  se = (SmemEpi*)smem_raw;

    const int b = blockIdx.y;
    const int tile = blockIdx.x;
    const int t0 = tile * TB_;
    const int tid = threadIdx.x;
    const int tx = tid & 15;    // dims d = tx*8 .. +7 (4 f32x2 pairs)
    const int ty = tid >> 4;    // tokens t = ty*4 .. +3

    u64 acc[4][4];
#pragma unroll
    for (int i = 0; i < 4; i++)
#pragma unroll
        for (int jp = 0; jp < 4; jp++) acc[i][jp] = 0ull;

    // global-load lane assignment
    const int ld_t  = tid >> 2;            // 0..63
    const int ld_kq = (tid & 3) * 4;       // 0,4,8,12
    const float* Drow = De + (size_t)(b*DL_ + t0 + ld_t)*H_ + ld_kq;
    const int w_d   = tid >> 1;            // 0..127
    const int w_kq0 = (tid & 1) * 8;       // 0 or 8
    const int w_kq1 = w_kq0 + 4;           // 4 or 12
    const float* Wrow = W + w_d*H_;

    float4 dv, wv0, wv1;

    // prologue: chunk 0 -> buf 0
    dv  = *(const float4*)(Drow);
    wv0 = *(const float4*)(Wrow + w_kq0);
    wv1 = *(const float4*)(Wrow + w_kq1);
    sm->DsT[0][ld_kq+0][ld_t] = dv.x; sm->DsT[0][ld_kq+1][ld_t] = dv.y;
    sm->DsT[0][ld_kq+2][ld_t] = dv.z; sm->DsT[0][ld_kq+3][ld_t] = dv.w;
    sm->WsT[0][w_kq0+0][w_d] = wv0.x; sm->WsT[0][w_kq0+1][w_d] = wv0.y;
    sm->WsT[0][w_kq0+2][w_d] = wv0.z; sm->WsT[0][w_kq0+3][w_d] = wv0.w;
    sm->WsT[0][w_kq1+0][w_d] = wv1.x; sm->WsT[0][w_kq1+1][w_d] = wv1.y;
    sm->WsT[0][w_kq1+2][w_d] = wv1.z; sm->WsT[0][w_kq1+3][w_d] = wv1.w;

    for (int c = 0; c < NCHUNK_; c++) {
        __syncthreads();
        const int buf = c & 1;
        if (c + 1 < NCHUNK_) {
            const int kc = (c+1) * KC_;
            dv  = *(const float4*)(Drow + kc);
            wv0 = *(const float4*)(Wrow + kc + w_kq0);
            wv1 = *(const float4*)(Wrow + kc + w_kq1);
        }
#pragma unroll
        for (int kk = 0; kk < KC_; kk++) {
            float4 av = *(const float4*)&sm->DsT[buf][kk][ty*4];
            u64 a0 = pack2(av.x, av.x);
            u64 a1 = pack2(av.y, av.y);
            u64 a2 = pack2(av.z, av.z);
            u64 a3 = pack2(av.w, av.w);
            ulonglong2 b01 = *(const ulonglong2*)&sm->WsT[buf][kk][tx*8];
            ulonglong2 b23 = *(const ulonglong2*)&sm->WsT[buf][kk][tx*8+4];
            fma2(acc[0][0], a0, b01.x); fma2(acc[0][1], a0, b01.y);
            fma2(acc[0][2], a0, b23.x); fma2(acc[0][3], a0, b23.y);
            fma2(acc[1][0], a1, b01.x); fma2(acc[1][1], a1, b01.y);
            fma2(acc[1][2], a1, b23.x); fma2(acc[1][3], a1, b23.y);
            fma2(acc[2][0], a2, b01.x); fma2(acc[2][1], a2, b01.y);
            fma2(acc[2][2], a2, b23.x); fma2(acc[2][3], a2, b23.y);
            fma2(acc[3][0], a3, b01.x); fma2(acc[3][1], a3, b01.y);
            fma2(acc[3][2], a3, b23.x); fma2(acc[3][3], a3, b23.y);
        }
        if (c + 1 < NCHUNK_) {
            const int nb = buf ^ 1;   // safe: last read of nb retired before the sync above
            sm->DsT[nb][ld_kq+0][ld_t] = dv.x; sm->DsT[nb][ld_kq+1][ld_t] = dv.y;
            sm->DsT[nb][ld_kq+2][ld_t] = dv.z; sm->DsT[nb][ld_kq+3][ld_t] = dv.w;
            sm->WsT[nb][w_kq0+0][w_d] = wv0.x; sm->WsT[nb][w_kq0+1][w_d] = wv0.y;
            sm->WsT[nb][w_kq0+2][w_d] = wv0.z; sm->WsT[nb][w_kq0+3][w_d] = wv0.w;
            sm->WsT[nb][w_kq1+0][w_d] = wv1.x; sm->WsT[nb][w_kq1+1][w_d] = wv1.y;
            sm->WsT[nb][w_kq1+2][w_d] = wv1.z; sm->WsT[nb][w_kq1+3][w_d] = wv1.w;
        }
    }
    __syncthreads();   // all compute on sm done

    // ---- epilogue phase 1: per-token sumsq (regs), masks + Qn -> smem ----
    float ss[4];
#pragma unroll
    for (int i = 0; i < 4; i++) {
        float s = 0.0f;
#pragma unroll
        for (int jp = 0; jp < 4; jp++) {
            float2 f = unpack2(acc[i][jp]);
            s += f.x*f.x + f.y*f.y;
        }
#pragma unroll
        for (int m = 1; m < 16; m <<= 1) s += __shfl_xor_sync(0xffffffffu, s, m);
        ss[i] = s;
    }
    if (tid < TB_) {   // region disjoint from SmemMain
        se->dsq[tid]  = (ids[b*DL_ + t0 + tid] != 0) ? 1.0f : 0.0f;
        se->keep[tid] = attn[b*DL_ + t0 + tid];
    }
    for (int r = tid; r < QL_*DIM_; r += 256)
        se->Qs[r >> 7][r & 127] = g_Qn[b*QL_*DIM_ + r];
    __syncthreads();

    // ---- epilogue phase 2: normalize + store DnT (overwrites SmemMain) ----
#pragma unroll
    for (int i = 0; i < 4; i++) {
        const int t = ty*4 + i;
        const float punct = se->dsq[t];
        const float inv = (punct > 0.0f) ? rsqrtf(fmaxf(ss[i], 1e-24f)) : 0.0f;
#pragma unroll
        for (int jp = 0; jp < 4; jp++) {
            float2 f = unpack2(acc[i][jp]);
            se->DnT[tx*8 + jp*2 + 0][t] = f.x * inv;
            se->DnT[tx*8 + jp*2 + 1][t] = f.y * inv;
        }
    }
    __syncthreads();

    // ---- epilogue phase 3: scoring GEMM [32q x 64t], masked max ----
    const int q  = tid >> 3;      // 0..31
    const int tj = tid & 7;       // token octet: t = tj*8 + jj
    u64 qd2[4] = {0ull, 0ull, 0ull, 0ull};
#pragma unroll 4
    for (int k = 0; k < DIM_; k++) {
        float qv = se->Qs[q][k];
        u64 q2 = pack2(qv, qv);
        const u64* dn = (const u64*)&se->DnT[k][tj*8];
        fma2(qd2[0], q2, dn[0]); fma2(qd2[1], q2, dn[1]);
        fma2(qd2[2], q2, dn[2]); fma2(qd2[3], q2, dn[3]);
    }
    float m = -3.0e38f;
#pragma unroll
    for (int p = 0; p < 4; p++) {
        float2 f = unpack2(qd2[p]);
        const int ta = tj*8 + p*2;
        float s0 = 2.0f*f.x - 1.0f - se->dsq[ta];
        s0 = se->keep[ta]   ? s0 : NEG_;
        float s1 = 2.0f*f.y - 1.0f - se->dsq[ta+1];
        s1 = se->keep[ta+1] ? s1 : NEG_;
        m = fmaxf(m, fmaxf(s0, s1));
    }
#pragma unroll
    for (int o = 1; o < 8; o <<= 1) m = fmaxf(m, __shfl_xor_sync(0xffffffffu, m, o));
    if (tj == 0) g_partial[(b*QL_ + q)*NT_ + tile] = m;
}

// ---------------------------------------------------------------------------
// Kernel 3: reduce partials -> out[B]
// ---------------------------------------------------------------------------
__global__ void r_kernel(float* __restrict__ out) {
    const int b = blockIdx.x;
    const int q = threadIdx.x;      // 32 threads
    float m = -3.0e38f;
#pragma unroll
    for (int i = 0; i < NT_; i++)
        m = fmaxf(m, g_partial[(b*QL_ + q)*NT_ + i]);
#pragma unroll
    for (int o = 16; o >= 1; o >>= 1) m += __shfl_xor_sync(0xffffffffu, m, o);
    if (q == 0) out[b] = m;
}

// ---------------------------------------------------------------------------
extern "C" void kernel_launch(void* const* d_in, const int* in_sizes, int n_in,
                              void* d_out, int out_size) {
    const float* Qe  = (const float*)d_in[0];
    const float* De  = (const float*)d_in[1];
    const int*   ids = (const int*)d_in[2];
    const int*   atn = (const int*)d_in[3];
    const float* W   = (const float*)d_in[4];
    float* out = (float*)d_out;

    const int smem = (sizeof(SmemEpi) > sizeof(SmemMain)) ? (int)sizeof(SmemEpi)
                                                          : (int)sizeof(SmemMain);
    cudaFuncSetAttribute(d_kernel, cudaFuncAttributeMaxDynamicSharedMemorySize, smem);

    q_kernel<<<B_, 256>>>(Qe, W);
    d_kernel<<<dim3(NT_, B_), 256, smem>>>(De, ids, atn, W);
    r_kernel<<<B_, 32>>>(out);
}

// round 11
// speedup vs baseline: 1.4665x; 1.4665x over previous
#include <cuda_runtime.h>

// ---------------------------------------------------------------------------
// ColBERT scoring, fp32, f32x2 FMA SIMT v2.
//  - dup-operand smem layout (no pack MOVs in mainloop)
//  - 128x128 CTA tile, 8tok x 8dim thread tile, KC=8 double-buffered
//  - swizzled DnT epilogue (conflict-free STS.64/LDS.64)
// ---------------------------------------------------------------------------

#define B_   128
#define QL_  32
#define DL_  1024
#define H_   768
#define DIM_ 128
#define TB_  128           // doc tokens per CTA
#define KC_  8             // K chunk (d_kernel)
#define NT_  (DL_/TB_)     // 8 tiles per batch
#define NCH_ (H_/KC_)      // 96
#define QKC_ 16            // K chunk (q_kernel)
#define QNCH_ (H_/QKC_)    // 48
#define NEG_ (-100000.0f)

__device__ float g_Qn[B_*QL_*DIM_];
__device__ float g_partial[B_*QL_*NT_];

typedef unsigned long long u64;

__device__ __forceinline__ u64 pack2(float x, float y) {
    u64 r; asm("mov.b64 %0, {%1, %2};" : "=l"(r) : "f"(x), "f"(y)); return r;
}
__device__ __forceinline__ float2 unpack2(u64 v) {
    float2 r; asm("mov.b64 {%0, %1}, %2;" : "=f"(r.x), "=f"(r.y) : "l"(v)); return r;
}
__device__ __forceinline__ void fma2(u64& d, u64 a, u64 b) {
    asm("fma.rn.f32x2 %0, %1, %2, %0;" : "+l"(d) : "l"(a), "l"(b));
}

// ---------------------------------------------------------------------------
// Kernel 1: Q projection + L2 normalize. One CTA/batch, 32q x 128d, f32x2.
// ---------------------------------------------------------------------------
__global__ __launch_bounds__(256)
void q_kernel(const float* __restrict__ Qe, const float* __restrict__ W) {
    __shared__ float Qd[2][QKC_][2*QL_];    // dup: [k][2q]=v,[2q+1]=v
    __shared__ float Ws[2][QKC_][DIM_];
    const int tid = threadIdx.x;
    const int b   = blockIdx.x;
    const int tx  = tid & 15;               // dims d = tx*8 .. +7
    const int ty  = tid >> 4;               // queries q = ty*2, ty*2+1

    u64 acc[2][4];
#pragma unroll
    for (int i = 0; i < 2; i++)
#pragma unroll
        for (int j = 0; j < 4; j++) acc[i][j] = 0ull;

    const int q_l  = tid >> 3;              // 0..31
    const int q_kq = (tid & 7) * 2;         // 0..14
    const float* Qrow = Qe + (size_t)(b*QL_ + q_l)*H_ + q_kq;
    const int w_d  = tid >> 1;              // 0..127
    const int w_kq = (tid & 1) * 8;         // 0 or 8
    const float* Wrow = W + (size_t)w_d*H_ + w_kq;

    float2 qv; float4 wv0, wv1;
    qv  = *(const float2*)Qrow;
    wv0 = *(const float4*)(Wrow);
    wv1 = *(const float4*)(Wrow + 4);
    *(u64*)&Qd[0][q_kq+0][2*q_l] = pack2(qv.x, qv.x);
    *(u64*)&Qd[0][q_kq+1][2*q_l] = pack2(qv.y, qv.y);
    Ws[0][w_kq+0][w_d] = wv0.x; Ws[0][w_kq+1][w_d] = wv0.y;
    Ws[0][w_kq+2][w_d] = wv0.z; Ws[0][w_kq+3][w_d] = wv0.w;
    Ws[0][w_kq+4][w_d] = wv1.x; Ws[0][w_kq+5][w_d] = wv1.y;
    Ws[0][w_kq+6][w_d] = wv1.z; Ws[0][w_kq+7][w_d] = wv1.w;

#pragma unroll 1
    for (int c = 0; c < QNCH_; c++) {
        __syncthreads();
        const int buf = c & 1;
        if (c + 1 < QNCH_) {
            const int kc = (c+1)*QKC_;
            qv  = *(const float2*)(Qrow + kc);
            wv0 = *(const float4*)(Wrow + kc);
            wv1 = *(const float4*)(Wrow + kc + 4);
        }
#pragma unroll
        for (int kk = 0; kk < QKC_; kk++) {
            ulonglong2 A = *(const ulonglong2*)&Qd[buf][kk][ty*4];
            const ulonglong2* bp = (const ulonglong2*)&Ws[buf][kk][tx*8];
            ulonglong2 B0 = bp[0], B1 = bp[1];
            fma2(acc[0][0], A.x, B0.x); fma2(acc[0][1], A.x, B0.y);
            fma2(acc[0][2], A.x, B1.x); fma2(acc[0][3], A.x, B1.y);
            fma2(acc[1][0], A.y, B0.x); fma2(acc[1][1], A.y, B0.y);
            fma2(acc[1][2], A.y, B1.x); fma2(acc[1][3], A.y, B1.y);
        }
        if (c + 1 < QNCH_) {
            const int nb = (c+1) & 1;
            *(u64*)&Qd[nb][q_kq+0][2*q_l] = pack2(qv.x, qv.x);
            *(u64*)&Qd[nb][q_kq+1][2*q_l] = pack2(qv.y, qv.y);
            Ws[nb][w_kq+0][w_d] = wv0.x; Ws[nb][w_kq+1][w_d] = wv0.y;
            Ws[nb][w_kq+2][w_d] = wv0.z; Ws[nb][w_kq+3][w_d] = wv0.w;
            Ws[nb][w_kq+4][w_d] = wv1.x; Ws[nb][w_kq+5][w_d] = wv1.y;
            Ws[nb][w_kq+6][w_d] = wv1.z; Ws[nb][w_kq+7][w_d] = wv1.w;
        }
    }

#pragma unroll
    for (int i = 0; i < 2; i++) {
        float ss = 0.0f;
#pragma unroll
        for (int j = 0; j < 4; j++) {
            float2 f = unpack2(acc[i][j]);
            ss += f.x*f.x + f.y*f.y;
        }
#pragma unroll
        for (int m = 1; m < 16; m <<= 1) ss += __shfl_xor_sync(0xffffffffu, ss, m);
        const float inv = rsqrtf(fmaxf(ss, 1e-24f));
        const int q = ty*2 + i;
#pragma unroll
        for (int j = 0; j < 4; j++) {
            float2 f = unpack2(acc[i][j]);
            *(u64*)&g_Qn[(b*QL_ + q)*DIM_ + tx*8 + 2*j] = pack2(f.x*inv, f.y*inv);
        }
    }
}

// ---------------------------------------------------------------------------
// Kernel 2: D projection + normalize + scoring + masked max. 128x128 tile.
// ---------------------------------------------------------------------------
struct __align__(16) SmemMain {
    float Dd[2][KC_][2*TB_];    // dup tokens: 16 KB
    float Ws[2][KC_][DIM_];     // 8 KB
};
struct __align__(16) SmemEpi {
    float DnT[DIM_][132];       // [dim][token-pair swizzled], 67.6 KB
    float Qs[QL_][132];         // 16.9 KB
    float dsq[TB_];             // punct ? 1 : 0
    int   keep[TB_];            // attn mask
};

extern __shared__ char smem_raw[];

__global__ __launch_bounds__(256, 2)
void d_kernel(const float* __restrict__ De, const int* __restrict__ ids,
              const int* __restrict__ attn, const float* __restrict__ W) {
    SmemMain* sm = (SmemMain*)smem_raw;
    SmemEpi*  se = (SmemEpi*)smem_raw;

    const int b    = blockIdx.y;
    const int tile = blockIdx.x;
    const int t0   = tile * TB_;
    const int tid  = threadIdx.x;
    const int tx   = tid & 15;      // dims d = tx*8 .. +7
    const int ty   = tid >> 4;      // tokens t = ty*8 .. +7

    u64 acc[8][4];
#pragma unroll
    for (int i = 0; i < 8; i++)
#pragma unroll
        for (int j = 0; j < 4; j++) acc[i][j] = 0ull;

    const int ld_t = tid >> 1;            // 0..127 (token for D, dim for W)
    const int ld_k = (tid & 1) * 4;       // 0 or 4
    const float* Drow = De + (size_t)(b*DL_ + t0 + ld_t)*H_ + ld_k;
    const float* Wrow = W  + (size_t)ld_t*H_ + ld_k;

    float4 dv, wv;
    dv = *(const float4*)Drow;
    wv = *(const float4*)Wrow;
    *(u64*)&sm->Dd[0][ld_k+0][2*ld_t] = pack2(dv.x, dv.x);
    *(u64*)&sm->Dd[0][ld_k+1][2*ld_t] = pack2(dv.y, dv.y);
    *(u64*)&sm->Dd[0][ld_k+2][2*ld_t] = pack2(dv.z, dv.z);
    *(u64*)&sm->Dd[0][ld_k+3][2*ld_t] = pack2(dv.w, dv.w);
    sm->Ws[0][ld_k+0][ld_t] = wv.x; sm->Ws[0][ld_k+1][ld_t] = wv.y;
    sm->Ws[0][ld_k+2][ld_t] = wv.z; sm->Ws[0][ld_k+3][ld_t] = wv.w;

#pragma unroll 1
    for (int c = 0; c < NCH_; c++) {
        __syncthreads();
        const int buf = c & 1;
        if (c + 1 < NCH_) {
            const int kc = (c+1) * KC_;
            dv = *(const float4*)(Drow + kc);
            wv = *(const float4*)(Wrow + kc);
        }
#pragma unroll
        for (int kk = 0; kk < KC_; kk++) {
            const ulonglong2* ap = (const ulonglong2*)&sm->Dd[buf][kk][ty*16];
            ulonglong2 A0 = ap[0], A1 = ap[1], A2 = ap[2], A3 = ap[3];
            const ulonglong2* bp = (const ulonglong2*)&sm->Ws[buf][kk][tx*8];
            ulonglong2 B0 = bp[0], B1 = bp[1];
            fma2(acc[0][0], A0.x, B0.x); fma2(acc[0][1], A0.x, B0.y);
            fma2(acc[0][2], A0.x, B1.x); fma2(acc[0][3], A0.x, B1.y);
            fma2(acc[1][0], A0.y, B0.x); fma2(acc[1][1], A0.y, B0.y);
            fma2(acc[1][2], A0.y, B1.x); fma2(acc[1][3], A0.y, B1.y);
            fma2(acc[2][0], A1.x, B0.x); fma2(acc[2][1], A1.x, B0.y);
            fma2(acc[2][2], A1.x, B1.x); fma2(acc[2][3], A1.x, B1.y);
            fma2(acc[3][0], A1.y, B0.x); fma2(acc[3][1], A1.y, B0.y);
            fma2(acc[3][2], A1.y, B1.x); fma2(acc[3][3], A1.y, B1.y);
            fma2(acc[4][0], A2.x, B0.x); fma2(acc[4][1], A2.x, B0.y);
            fma2(acc[4][2], A2.x, B1.x); fma2(acc[4][3], A2.x, B1.y);
            fma2(acc[5][0], A2.y, B0.x); fma2(acc[5][1], A2.y, B0.y);
            fma2(acc[5][2], A2.y, B1.x); fma2(acc[5][3], A2.y, B1.y);
            fma2(acc[6][0], A3.x, B0.x); fma2(acc[6][1], A3.x, B0.y);
            fma2(acc[6][2], A3.x, B1.x); fma2(acc[6][3], A3.x, B1.y);
            fma2(acc[7][0], A3.y, B0.x); fma2(acc[7][1], A3.y, B0.y);
            fma2(acc[7][2], A3.y, B1.x); fma2(acc[7][3], A3.y, B1.y);
        }
        if (c + 1 < NCH_) {
            const int nb = (c+1) & 1;
            *(u64*)&sm->Dd[nb][ld_k+0][2*ld_t] = pack2(dv.x, dv.x);
            *(u64*)&sm->Dd[nb][ld_k+1][2*ld_t] = pack2(dv.y, dv.y);
            *(u64*)&sm->Dd[nb][ld_k+2][2*ld_t] = pack2(dv.z, dv.z);
            *(u64*)&sm->Dd[nb][ld_k+3][2*ld_t] = pack2(dv.w, dv.w);
            sm->Ws[nb][ld_k+0][ld_t] = wv.x; sm->Ws[nb][ld_k+1][ld_t] = wv.y;
            sm->Ws[nb][ld_k+2][ld_t] = wv.z; sm->Ws[nb][ld_k+3][ld_t] = wv.w;
        }
    }
    __syncthreads();   // (a) mainloop smem dead

    // ---- per-token sumsq (regs) + stage Qn & masks ----
    float ss[8];
#pragma unroll
    for (int i = 0; i < 8; i++) {
        float s = 0.0f;
#pragma unroll
        for (int j = 0; j < 4; j++) {
            float2 f = unpack2(acc[i][j]);
            s += f.x*f.x + f.y*f.y;
        }
#pragma unroll
        for (int m = 1; m < 16; m <<= 1) s += __shfl_xor_sync(0xffffffffu, s, m);
        ss[i] = s;
    }
    if (tid < TB_) {
        se->dsq[tid]  = (ids[b*DL_ + t0 + tid] != 0) ? 1.0f : 0.0f;
        se->keep[tid] = attn[b*DL_ + t0 + tid];
    }
    for (int r = tid; r < QL_*DIM_; r += 256)
        se->Qs[r >> 7][r & 127] = g_Qn[b*QL_*DIM_ + r];
    __syncthreads();   // (b) masks/Qs visible

    // ---- normalize + store DnT[dim][pair ^ swz] as token-pairs ----
    float inv[8];
#pragma unroll
    for (int i = 0; i < 8; i++) {
        const float punct = se->dsq[ty*8 + i];
        inv[i] = (punct > 0.0f) ? rsqrtf(fmaxf(ss[i], 1e-24f)) : 0.0f;
    }
#pragma unroll
    for (int ii = 0; ii < 8; ii += 2) {
        const int P   = ty*4 + (ii >> 1);
        const int col = 2 * (P ^ tx);      // swz(row)= (row>>3)&15 = tx for all our rows
#pragma unroll
        for (int j = 0; j < 4; j++) {
            float2 f0 = unpack2(acc[ii][j]);
            float2 f1 = unpack2(acc[ii+1][j]);
            const int d0 = tx*8 + 2*j;
            *(u64*)&se->DnT[d0  ][col] = pack2(f0.x*inv[ii], f1.x*inv[ii+1]);
            *(u64*)&se->DnT[d0+1][col] = pack2(f0.y*inv[ii], f1.y*inv[ii+1]);
        }
    }
    __syncthreads();   // (c) DnT ready

    // ---- scoring GEMM 32q x 128t, K=128, masked max ----
    const int tj = tid & 15;       // token-pair class
    const int qh = tid >> 4;       // q = qh*2, qh*2+1
    u64 a2[2][4];
#pragma unroll
    for (int qi = 0; qi < 2; qi++)
#pragma unroll
        for (int m = 0; m < 4; m++) a2[qi][m] = 0ull;

#pragma unroll 4
    for (int k = 0; k < DIM_; k++) {
        const int s = (k >> 3) & 15;
        const float qv0 = se->Qs[qh*2  ][k];
        const float qv1 = se->Qs[qh*2+1][k];
        const u64 q0 = pack2(qv0, qv0);
        const u64 q1 = pack2(qv1, qv1);
#pragma unroll
        for (int m = 0; m < 4; m++) {
            const u64 dp = *(const u64*)&se->DnT[k][2*((tj + 16*m) ^ s)];
            fma2(a2[0][m], q0, dp);
            fma2(a2[1][m], q1, dp);
        }
    }
#pragma unroll
    for (int qi = 0; qi < 2; qi++) {
        float mq = -3.0e38f;
#pragma unroll
        for (int m = 0; m < 4; m++) {
            float2 f = unpack2(a2[qi][m]);
            const int t = 2*(tj + 16*m);
            float s0 = 2.0f*f.x - 1.0f - se->dsq[t];
            s0 = se->keep[t]   ? s0 : NEG_;
            float s1 = 2.0f*f.y - 1.0f - se->dsq[t+1];
            s1 = se->keep[t+1] ? s1 : NEG_;
            mq = fmaxf(mq, fmaxf(s0, s1));
        }
#pragma unroll
        for (int o = 1; o < 16; o <<= 1)
            mq = fmaxf(mq, __shfl_xor_sync(0xffffffffu, mq, o));
        if (tj == 0)
            g_partial[(b*QL_ + qh*2 + qi)*NT_ + tile] = mq;
    }
}

// ---------------------------------------------------------------------------
// Kernel 3: reduce partials -> out[B]
// ---------------------------------------------------------------------------
__global__ void r_kernel(float* __restrict__ out) {
    const int b = blockIdx.x;
    const int q = threadIdx.x;      // 32 threads
    float m = -3.0e38f;
#pragma unroll
    for (int i = 0; i < NT_; i++)
        m = fmaxf(m, g_partial[(b*QL_ + q)*NT_ + i]);
#pragma unroll
    for (int o = 16; o >= 1; o >>= 1) m += __shfl_xor_sync(0xffffffffu, m, o);
    if (q == 0) out[b] = m;
}

// ---------------------------------------------------------------------------
extern "C" void kernel_launch(void* const* d_in, const int* in_sizes, int n_in,
                              void* d_out, int out_size) {
    const float* Qe  = (const float*)d_in[0];
    const float* De  = (const float*)d_in[1];
    const int*   ids = (const int*)d_in[2];
    const int*   atn = (const int*)d_in[3];
    const float* W   = (const float*)d_in[4];
    float* out = (float*)d_out;

    const int smem = (sizeof(SmemEpi) > sizeof(SmemMain)) ? (int)sizeof(SmemEpi)
                                                          : (int)sizeof(SmemMain);
    cudaFuncSetAttribute(d_kernel, cudaFuncAttributeMaxDynamicSharedMemorySize, smem);

    q_kernel<<<B_, 256>>>(Qe, W);
    d_kernel<<<dim3(NT_, B_), 256, smem>>>(De, ids, atn, W);
    r_kernel<<<B_, 32>>>(out);
}

// round 15
// speedup vs baseline: 3.1341x; 2.1371x over previous
#include <cuda_runtime.h>
#include <cstdint>

// ---------------------------------------------------------------------------
// ColBERT scoring v4 — mma.sync (bf16 HMMA, portable PTX) D-projection.
//   W pre-split to bf16 hi/lo planes once; De converted to single rn-bf16
//   in-kernel.  D = A_bf16*(Whi + Wlo), fp32 accum.  Epilogue: normalize +
//   32q x 128t f32x2 scoring GEMM + masked max (v2/v3 proven machinery).
// ---------------------------------------------------------------------------

#define B_   128
#define QL_  32
#define DL_  1024
#define H_   768
#define DIM_ 128
#define TB_  128
#define NT_  (DL_/TB_)      // 8
#define KC_  32             // K per chunk
#define NCH_ (H_/KC_)       // 24
#define NEG_ (-100000.0f)
#define TBP_ 132            // DNT token stride (conflict-free)

typedef unsigned int u32;
typedef unsigned long long u64;

__device__ float g_Qn[B_*QL_*DIM_];
__device__ float g_partial[B_*QL_*NT_];
// pre-packed W planes: [chunk][dim][k-in-chunk] bf16
__device__ __align__(16) unsigned short g_Whi[NCH_*DIM_*KC_];
__device__ __align__(16) unsigned short g_Wlo[NCH_*DIM_*KC_];

// smem byte offsets (d_kernel). Mainloop tiles (80B row stride, ldmatrix
// conflict-free) overlap DNT; epilogue regions live above 67584.
#define SM_A    0                     // 128*80 = 10240
#define SM_WH   10240                 // 10240
#define SM_WL   20480                 // 10240 -> 30720
#define SM_DNT  0                     // 128*132*4 = 67584
#define SM_QS   67584                 // 32*128*4 = 16384 -> 83968
#define SM_PART 83968                 // 128*2*4 = 1024 -> 84992
#define SM_DSQ  84992                 // 512
#define SM_KEEP 85504                 // 512 -> 86016
#define SMEM_TOTAL 86016

// ---------------- helpers --------------------------------------------------
__device__ __forceinline__ u32 smem_u32(const void* p) {
    u32 a; asm("{ .reg .u64 t; cvta.to.shared.u64 t, %1; cvt.u32.u64 %0, t; }"
               : "=r"(a) : "l"(p));
    return a;
}
// pack {hi16 = bf16(hv), lo16 = bf16(lv)}
__device__ __forceinline__ u32 cvt_bf2(float hv, float lv) {
    u32 r; asm("cvt.rn.satfinite.bf16x2.f32 %0, %1, %2;" : "=r"(r) : "f"(hv), "f"(lv));
    return r;
}
__device__ __forceinline__ void ldm4(u32* d, u32 addr) {
    asm volatile("ldmatrix.sync.aligned.m8n8.x4.shared.b16 {%0,%1,%2,%3}, [%4];"
        : "=r"(d[0]), "=r"(d[1]), "=r"(d[2]), "=r"(d[3]) : "r"(addr));
}
__device__ __forceinline__ void mma16816(float* c, const u32* a, u32 b0, u32 b1) {
    asm volatile("mma.sync.aligned.m16n8k16.row.col.f32.bf16.bf16.f32 "
        "{%0,%1,%2,%3}, {%4,%5,%6,%7}, {%8,%9}, {%0,%1,%2,%3};"
        : "+f"(c[0]), "+f"(c[1]), "+f"(c[2]), "+f"(c[3])
        : "r"(a[0]), "r"(a[1]), "r"(a[2]), "r"(a[3]), "r"(b0), "r"(b1));
}
__device__ __forceinline__ u64 pack2(float x, float y) {
    u64 r; asm("mov.b64 %0, {%1, %2};" : "=l"(r) : "f"(x), "f"(y)); return r;
}
__device__ __forceinline__ float2 unpack2(u64 v) {
    float2 r; asm("mov.b64 {%0, %1}, %2;" : "=f"(r.x), "=f"(r.y) : "l"(v)); return r;
}
__device__ __forceinline__ void fma2(u64& d, u64 a, u64 b) {
    asm("fma.rn.f32x2 %0, %1, %2, %0;" : "+l"(d) : "l"(a), "l"(b));
}

// ---------------------------------------------------------------------------
// Kernel 0: split W -> bf16 hi/lo packed planes. 24576 float4s.
// ---------------------------------------------------------------------------
__global__ void w_kernel(const float* __restrict__ Wt) {
    int idx = blockIdx.x * 256 + threadIdx.x;
    if (idx >= DIM_*H_/4) return;
    int dim = idx / (H_/4);
    int k4  = (idx % (H_/4)) * 4;
    float4 v = *(const float4*)(Wt + (size_t)dim*H_ + k4);
    u32 h0 = cvt_bf2(v.y, v.x);
    u32 h1 = cvt_bf2(v.w, v.z);
    float e0 = __uint_as_float(h0 << 16);
    float e1 = __uint_as_float(h0 & 0xFFFF0000u);
    float e2 = __uint_as_float(h1 << 16);
    float e3 = __uint_as_float(h1 & 0xFFFF0000u);
    u32 l0 = cvt_bf2(v.y - e1, v.x - e0);
    u32 l1 = cvt_bf2(v.w - e3, v.z - e2);
    int c   = k4 >> 5;
    int kin = k4 & 31;
    u32 off = ((u32)c*DIM_ + dim)*KC_ + kin;
    *(uint2*)&g_Whi[off] = make_uint2(h0, h1);
    *(uint2*)&g_Wlo[off] = make_uint2(l0, l1);
}

// ---------------------------------------------------------------------------
// Kernel 1: Q projection + L2 normalize (fp32 SIMT). grid (B, 4), 8q/CTA.
// ---------------------------------------------------------------------------
__global__ __launch_bounds__(256)
void q_kernel(const float* __restrict__ Qe, const float* __restrict__ Wt) {
    __shared__ __align__(16) float QsT[16][12];
    __shared__ __align__(16) float WsT[16][132];
    const int tid = threadIdx.x;
    const int b = blockIdx.x, qc = blockIdx.y;
    const int ty = tid >> 5;        // query 0..7
    const int tx = tid & 31;        // dims tx*4..+3
    float acc[4] = {0.f, 0.f, 0.f, 0.f};

    for (int c = 0; c < H_/16; c++) {
        const int kc = c*16;
        __syncthreads();
        if (tid < 32) {
            int q = tid >> 2, k4 = (tid & 3) * 4;
            float4 v = *(const float4*)(Qe + (size_t)(b*QL_ + qc*8 + q)*H_ + kc + k4);
            QsT[k4+0][q]=v.x; QsT[k4+1][q]=v.y; QsT[k4+2][q]=v.z; QsT[k4+3][q]=v.w;
        }
#pragma unroll
        for (int r2 = 0; r2 < 2; r2++) {
            int idx = tid*2 + r2;
            int d = idx >> 2, k4 = (idx & 3) * 4;
            float4 w = *(const float4*)(Wt + (size_t)d*H_ + kc + k4);
            WsT[k4+0][d]=w.x; WsT[k4+1][d]=w.y; WsT[k4+2][d]=w.z; WsT[k4+3][d]=w.w;
        }
        __syncthreads();
#pragma unroll
        for (int kk = 0; kk < 16; kk++) {
            float qv = QsT[kk][ty];
            float4 w = *(const float4*)&WsT[kk][tx*4];
            acc[0] += qv*w.x; acc[1] += qv*w.y; acc[2] += qv*w.z; acc[3] += qv*w.w;
        }
    }
    float ss = acc[0]*acc[0] + acc[1]*acc[1] + acc[2]*acc[2] + acc[3]*acc[3];
#pragma unroll
    for (int o = 1; o < 32; o <<= 1) ss += __shfl_xor_sync(0xffffffffu, ss, o);
    const float inv = rsqrtf(fmaxf(ss, 1e-24f));
    float4 ov; ov.x=acc[0]*inv; ov.y=acc[1]*inv; ov.z=acc[2]*inv; ov.w=acc[3]*inv;
    *(float4*)&g_Qn[(size_t)(b*QL_ + qc*8 + ty)*DIM_ + tx*4] = ov;
}

// ---------------------------------------------------------------------------
// Kernel 2: D projection via mma.sync bf16 + normalize + scoring + max.
// CTA tile 128 tok x 128 dim; 8 warps, each 32x64 (warp grid 4m x 2n).
// ---------------------------------------------------------------------------
extern __shared__ char smem_d[];

__global__ __launch_bounds__(256, 2)
void d_kernel(const float* __restrict__ De, const int* __restrict__ ids,
              const int* __restrict__ attn) {
    char* smem = smem_d;
    const int tid = threadIdx.x;
    const int l = tid & 31, wid = tid >> 5;
    const int wm = wid & 3, wn = wid >> 2;
    const int tile = blockIdx.x, b = blockIdx.y;
    const int t0 = tile * TB_;

    float acc[2][8][4];
#pragma unroll
    for (int mt = 0; mt < 2; mt++)
#pragma unroll
        for (int nt = 0; nt < 8; nt++)
#pragma unroll
            for (int j = 0; j < 4; j++) acc[mt][nt][j] = 0.f;

    // ldmatrix per-lane base addresses
    const int a_row = wm*32 + (l & 7) + 8*((l >> 3) & 1);
    const u32 a_base = smem_u32(smem + SM_A) + (u32)a_row*80 + (u32)(l >> 4)*16;
    const int b_row = wn*64 + (l & 7) + 8*(l >> 4);
    const u32 b_koff = ((u32)(l >> 3) & 1)*16;
    const u32 bh_base = smem_u32(smem + SM_WH) + (u32)b_row*80 + b_koff;
    const u32 bl_base = smem_u32(smem + SM_WL) + (u32)b_row*80 + b_koff;

    // staging pointers (thread t: A row t>>1, k-half t&1; W uint4 t and t+256)
    const float4* Ap = (const float4*)(De + (size_t)(b*DL_ + t0 + (tid >> 1))*H_
                                       + (tid & 1)*16);
    char* a_dst = smem + SM_A + (tid >> 1)*80 + (tid & 1)*32;

#pragma unroll 1
    for (int c = 0; c < NCH_; c++) {
        __syncthreads();   // previous compute done -> smem free
        // --- stage A (fp32 -> bf16) ---
        {
            const float4* ap = Ap + c*(KC_/4);
            float4 v0 = ap[0], v1 = ap[1], v2 = ap[2], v3 = ap[3];
            uint4 s0, s1;
            s0.x = cvt_bf2(v0.y, v0.x); s0.y = cvt_bf2(v0.w, v0.z);
            s0.z = cvt_bf2(v1.y, v1.x); s0.w = cvt_bf2(v1.w, v1.z);
            s1.x = cvt_bf2(v2.y, v2.x); s1.y = cvt_bf2(v2.w, v2.z);
            s1.z = cvt_bf2(v3.y, v3.x); s1.w = cvt_bf2(v3.w, v3.z);
            *(uint4*)(a_dst)      = s0;
            *(uint4*)(a_dst + 16) = s1;
        }
        // --- stage W planes (pre-converted, contiguous per chunk) ---
        {
            const u32 base = (u32)c * DIM_ * KC_;
#pragma unroll
            for (int rr = 0; rr < 2; rr++) {
                int u = tid + rr*256;           // uint4 index 0..511
                int dim = u >> 2, kq = (u & 3) * 8;
                uint4 wh = *(const uint4*)&g_Whi[base + (u32)dim*KC_ + kq];
                uint4 wl = *(const uint4*)&g_Wlo[base + (u32)dim*KC_ + kq];
                *(uint4*)(smem + SM_WH + dim*80 + kq*2) = wh;
                *(uint4*)(smem + SM_WL + dim*80 + kq*2) = wl;
            }
        }
        __syncthreads();   // tiles ready
        // --- compute: 2 k16 steps ---
#pragma unroll
        for (int kh = 0; kh < 2; kh++) {
            u32 afr[2][4];
            ldm4(afr[0], a_base + kh*32);
            ldm4(afr[1], a_base + kh*32 + 16*80);   // mt=1: +16 rows
            u32 bfr[4][4];
#pragma unroll
            for (int no = 0; no < 4; no++)
                ldm4(bfr[no], bh_base + kh*32 + (u32)no*16*80);
#pragma unroll
            for (int mt = 0; mt < 2; mt++)
#pragma unroll
                for (int no = 0; no < 4; no++) {
                    mma16816(acc[mt][2*no],   afr[mt], bfr[no][0], bfr[no][1]);
                    mma16816(acc[mt][2*no+1], afr[mt], bfr[no][2], bfr[no][3]);
                }
#pragma unroll
            for (int no = 0; no < 4; no++)
                ldm4(bfr[no], bl_base + kh*32 + (u32)no*16*80);
#pragma unroll
            for (int mt = 0; mt < 2; mt++)
#pragma unroll
                for (int no = 0; no < 4; no++) {
                    mma16816(acc[mt][2*no],   afr[mt], bfr[no][0], bfr[no][1]);
                    mma16816(acc[mt][2*no+1], afr[mt], bfr[no][2], bfr[no][3]);
                }
        }
    }
    __syncthreads();   // mainloop smem dead

    // ---- epilogue phase 1: masks + Qn staging, per-row sumsq partials ----
    float* QS   = (float*)(smem + SM_QS);
    float* PART = (float*)(smem + SM_PART);
    float* DSQ  = (float*)(smem + SM_DSQ);
    int*   KEEP = (int*)(smem + SM_KEEP);
    float* DNT  = (float*)(smem + SM_DNT);
    if (tid < TB_) {
        DSQ[tid]  = (ids[b*DL_ + t0 + tid] != 0) ? 1.0f : 0.0f;
        KEEP[tid] = attn[b*DL_ + t0 + tid];
    }
    for (int r = tid; r < QL_*DIM_; r += 256)
        QS[r] = g_Qn[b*QL_*DIM_ + r];

    float ssq[2][2] = {{0.f, 0.f}, {0.f, 0.f}};
#pragma unroll
    for (int mt = 0; mt < 2; mt++)
#pragma unroll
        for (int nt = 0; nt < 8; nt++) {
            ssq[mt][0] += acc[mt][nt][0]*acc[mt][nt][0] + acc[mt][nt][1]*acc[mt][nt][1];
            ssq[mt][1] += acc[mt][nt][2]*acc[mt][nt][2] + acc[mt][nt][3]*acc[mt][nt][3];
        }
#pragma unroll
    for (int o = 1; o < 4; o <<= 1) {
#pragma unroll
        for (int mt = 0; mt < 2; mt++) {
            ssq[mt][0] += __shfl_xor_sync(0xffffffffu, ssq[mt][0], o);
            ssq[mt][1] += __shfl_xor_sync(0xffffffffu, ssq[mt][1], o);
        }
    }
    const int r00 = wm*32 + (l >> 2);
    if ((l & 3) == 0) {
        PART[(r00     )*2 + wn] = ssq[0][0];
        PART[(r00 +  8)*2 + wn] = ssq[0][1];
        PART[(r00 + 16)*2 + wn] = ssq[1][0];
        PART[(r00 + 24)*2 + wn] = ssq[1][1];
    }
    __syncthreads();

    // ---- epilogue phase 2: normalize + scatter DNT[dim][tok] ----
    float inv[2][2];
#pragma unroll
    for (int mt = 0; mt < 2; mt++)
#pragma unroll
        for (int h = 0; h < 2; h++) {
            const int r = r00 + mt*16 + 8*h;
            const float s = PART[r*2] + PART[r*2 + 1];
            inv[mt][h] = (DSQ[r] > 0.f) ? rsqrtf(fmaxf(s, 1e-24f)) : 0.f;
        }
#pragma unroll
    for (int mt = 0; mt < 2; mt++)
#pragma unroll
        for (int nt = 0; nt < 8; nt++)
#pragma unroll
            for (int j = 0; j < 4; j++) {
                const int col = wn*64 + nt*8 + 2*(l & 3) + (j & 1);
                const int r   = r00 + mt*16 + 8*(j >> 1);
                DNT[col*TBP_ + r] = acc[mt][nt][j] * inv[mt][j >> 1];
            }
    __syncthreads();

    // ---- scoring GEMM 32q x 128t over K=128, masked max ----
    const int tj = tid & 15;
    const int qh = tid >> 4;
    u64 a2[2][4];
#pragma unroll
    for (int qi = 0; qi < 2; qi++)
#pragma unroll
        for (int m = 0; m < 4; m++) a2[qi][m] = 0ull;

#pragma unroll 4
    for (int k = 0; k < DIM_; k++) {
        const float qv0 = QS[(qh*2    )*DIM_ + k];
        const float qv1 = QS[(qh*2 + 1)*DIM_ + k];
        const u64 q0 = pack2(qv0, qv0);
        const u64 q1 = pack2(qv1, qv1);
#pragma unroll
        for (int m = 0; m < 4; m++) {
            const u64 dp = *(const u64*)&DNT[k*TBP_ + 2*(tj + 16*m)];
            fma2(a2[0][m], q0, dp);
            fma2(a2[1][m], q1, dp);
        }
    }
#pragma unroll
    for (int qi = 0; qi < 2; qi++) {
        float mq = -3.0e38f;
#pragma unroll
        for (int m = 0; m < 4; m++) {
            float2 f = unpack2(a2[qi][m]);
            const int tt = 2*(tj + 16*m);
            float s0 = 2.0f*f.x - 1.0f - DSQ[tt];
            s0 = KEEP[tt]   ? s0 : NEG_;
            float s1 = 2.0f*f.y - 1.0f - DSQ[tt+1];
            s1 = KEEP[tt+1] ? s1 : NEG_;
            mq = fmaxf(mq, fmaxf(s0, s1));
        }
#pragma unroll
        for (int o = 1; o < 16; o <<= 1)
            mq = fmaxf(mq, __shfl_xor_sync(0xffffffffu, mq, o));
        if (tj == 0)
            g_partial[(b*QL_ + qh*2 + qi)*NT_ + tile] = mq;
    }
}

// ---------------------------------------------------------------------------
// Kernel 3: reduce partials -> out[B]
// ---------------------------------------------------------------------------
__global__ void r_kernel(float* __restrict__ out) {
    const int b = blockIdx.x;
    const int q = threadIdx.x;
    float m = -3.0e38f;
#pragma unroll
    for (int i = 0; i < NT_; i++)
        m = fmaxf(m, g_partial[(b*QL_ + q)*NT_ + i]);
#pragma unroll
    for (int o = 16; o >= 1; o >>= 1) m += __shfl_xor_sync(0xffffffffu, m, o);
    if (q == 0) out[b] = m;
}

// ---------------------------------------------------------------------------
extern "C" void kernel_launch(void* const* d_in, const int* in_sizes, int n_in,
                              void* d_out, int out_size) {
    const float* Qe  = (const float*)d_in[0];
    const float* De  = (const float*)d_in[1];
    const int*   ids = (const int*)d_in[2];
    const int*   atn = (const int*)d_in[3];
    const float* W   = (const float*)d_in[4];
    float* out = (float*)d_out;

    cudaFuncSetAttribute(d_kernel, cudaFuncAttributeMaxDynamicSharedMemorySize,
                         SMEM_TOTAL);

    w_kernel<<<(DIM_*H_/4 + 255)/256, 256>>>(W);
    q_kernel<<<dim3(B_, 4), 256>>>(Qe, W);
    d_kernel<<<dim3(NT_, B_), 256, SMEM_TOTAL>>>(De, ids, atn);
    r_kernel<<<B_, 32>>>(out);
}